// round 2
// baseline (speedup 1.0000x reference)
#include <cuda_runtime.h>
#include <math.h>

#define D    4096
#define NT   256
#define NW   8
#define CAP  1536

__global__ void __launch_bounds__(NT)
entmax_bisect_kernel(const float* __restrict__ X, float* __restrict__ Y) {
    __shared__ float          srow[D];
    __shared__ float          svals[CAP];
    __shared__ unsigned short sidx[CAP];
    __shared__ float          swmax[NW];
    __shared__ int            swcnt[NW];

    const int row  = blockIdx.x;
    const int tid  = threadIdx.x;
    const int lane = tid & 31;
    const int wid  = tid >> 5;
    const size_t base = (size_t)row * D;

    const float4* __restrict__ xin  = reinterpret_cast<const float4*>(X + base);
    float4* __restrict__       yout = reinterpret_cast<float4*>(Y + base);
    float4* srow4 = reinterpret_cast<float4*>(srow);

    // ---- Pass 1: load row, scale by (alpha-1)=0.5 (exact), stage to smem, local max
    float lmax = -3.402823466e38f;
#pragma unroll
    for (int k = 0; k < 4; ++k) {
        float4 v = xin[tid + k * NT];
        v.x *= 0.5f; v.y *= 0.5f; v.z *= 0.5f; v.w *= 0.5f;
        srow4[tid + k * NT] = v;
        lmax = fmaxf(lmax, fmaxf(fmaxf(v.x, v.y), fmaxf(v.z, v.w)));
    }
#pragma unroll
    for (int o = 16; o; o >>= 1)
        lmax = fmaxf(lmax, __shfl_xor_sync(0xffffffffu, lmax, o));
    if (lane == 0) swmax[wid] = lmax;
    __syncthreads();
    float m = swmax[0];
#pragma unroll
    for (int w = 1; w < NW; ++w) m = fmaxf(m, swmax[w]);

    // ---- Pass 2: deterministic compaction of candidates Xs > m-1
    // (every tested t satisfies t > m-1, so nothing else can ever be active)
    const float tlow = m - 1.0f;
    int cnt = 0;
#pragma unroll
    for (int k = 0; k < 4; ++k) {
        float4 v = srow4[tid + k * NT];
        cnt += (v.x > tlow) + (v.y > tlow) + (v.z > tlow) + (v.w > tlow);
    }
    int incl = cnt;
#pragma unroll
    for (int o = 1; o < 32; o <<= 1) {
        int up = __shfl_up_sync(0xffffffffu, incl, o);
        if (lane >= o) incl += up;
    }
    if (lane == 31) swcnt[wid] = incl;
    __syncthreads();
    int wbase = 0, ntot = 0;
#pragma unroll
    for (int w = 0; w < NW; ++w) { int c = swcnt[w]; if (w < wid) wbase += c; ntot += c; }

    if (ntot <= CAP) {
        int pos = wbase + incl - cnt;
#pragma unroll
        for (int k = 0; k < 4; ++k) {
            float4 v = srow4[tid + k * NT];
            int e = (tid + k * NT) * 4;
            if (v.x > tlow) { svals[pos] = v.x; sidx[pos] = (unsigned short)(e    ); ++pos; }
            if (v.y > tlow) { svals[pos] = v.y; sidx[pos] = (unsigned short)(e + 1); ++pos; }
            if (v.z > tlow) { svals[pos] = v.z; sidx[pos] = (unsigned short)(e + 2); ++pos; }
            if (v.w > tlow) { svals[pos] = v.w; sidx[pos] = (unsigned short)(e + 3); ++pos; }
        }
    }
    __syncthreads();

    // ---- One warp bisects (rotated per-row to spread across SMSPs);
    //      the other 7 warps zero the output row concurrently.
    const int bw = row & (NW - 1);
    float  t = 0.0f, S = 1.0f;
    float* bv = svals;
    int    bn = 0;
    bool   useIdx = true;

    if (wid == bw) {
        const bool docompact = (ntot <= CAP);
        bv     = docompact ? svals : srow;   // fallback: scan full row (never in practice)
        bn     = docompact ? ntot  : D;
        useIdx = docompact;

        const float P = 1.0f / 4095.0f;      // p = 1/(d-1), faithful to reference
        float tmin = m - 1.0f;
        float diff = (m - 0.015625f) - tmin; // t_max - t_min in fp32, d^(1-alpha)=1/64 exact
        t = tmin;
        for (int it = 0; it < 50; ++it) {
            diff *= 0.5f;
            t = tmin + diff;
            if (t == tmin) break;            // fp32 fixpoint: remaining iters are no-ops
            float s = 0.0f;
            for (int j = lane; j < bn; j += 32) {
                float u = bv[j] - t;
                if (u > 0.0f) s += powf(u, P);
            }
#pragma unroll
            for (int o = 16; o; o >>= 1) s += __shfl_xor_sync(0xffffffffu, s, o);
            if (s - 1.0f >= 0.0f) {
                tmin = t;
                if (docompact) {
                    // in-place warp compaction: keep only v > tmin (future t > tmin)
                    int nn = 0;
                    for (int j0 = 0; j0 < bn; j0 += 32) {
                        int j = j0 + lane;
                        float v = 0.0f; unsigned short ix = 0;
                        bool keep = false;
                        if (j < bn) { v = bv[j]; ix = sidx[j]; keep = (v > tmin); }
                        __syncwarp();
                        unsigned b = __ballot_sync(0xffffffffu, keep);
                        if (keep) {
                            int p2 = nn + __popc(b & ((1u << lane) - 1u));
                            bv[p2] = v; sidx[p2] = ix;
                        }
                        nn += __popc(b);
                        __syncwarp();
                    }
                    bn = nn;
                }
            }
        }
        // final Z at the last tested t (reference semantics), plus its sum
        float s2 = 0.0f;
        for (int j = lane; j < bn; j += 32) {
            float u = bv[j] - t;
            float z = (u > 0.0f) ? powf(u, P) : 0.0f;
            bv[j] = z;
            s2 += z;
        }
#pragma unroll
        for (int o = 16; o; o >>= 1) s2 += __shfl_xor_sync(0xffffffffu, s2, o);
        S = s2;
    } else {
        // zero the whole output row (almost all outputs are exactly 0)
        int zw = wid - (wid > bw ? 1 : 0);
        float4 z4 = make_float4(0.0f, 0.0f, 0.0f, 0.0f);
        for (int i = zw * 32 + lane; i < D / 4; i += NT - 32) yout[i] = z4;
    }
    __syncthreads();   // zeros complete before scatter of nonzeros

    if (wid == bw) {
        for (int j = lane; j < bn; j += 32) {
            float z = bv[j];
            if (z > 0.0f) {
                int e = useIdx ? (int)sidx[j] : j;
                Y[base + e] = z / S;
            }
        }
    }
}

extern "C" void kernel_launch(void* const* d_in, const int* in_sizes, int n_in,
                              void* d_out, int out_size) {
    const float* X = (const float*)d_in[0];
    float*       Y = (float*)d_out;
    const int rows = out_size / D;   // 8*2048 = 16384
    entmax_bisect_kernel<<<rows, NT>>>(X, Y);
}

// round 3
// speedup vs baseline: 2.1435x; 2.1435x over previous
#include <cuda_runtime.h>
#include <math.h>

#define D  4096
#define NT 256
#define NW 8

__global__ void __launch_bounds__(NT)
entmax_bisect_kernel(const float* __restrict__ X, float* __restrict__ Y) {
    __shared__ float sm1[NW];
    __shared__ float sm2[NW];
    __shared__ float ssum[NW];

    const int tid  = threadIdx.x;
    const int lane = tid & 31;
    const int wid  = tid >> 5;
    const size_t base = (size_t)blockIdx.x * D;

    const float4* __restrict__ xin  = reinterpret_cast<const float4*>(X + base);
    float4* __restrict__       yout = reinterpret_cast<float4*>(Y + base);

    // ---- Load row into registers (16 floats/thread), scale by (alpha-1)=0.5 (exact),
    //      track per-thread (max, second-max) including duplicates.
    float4 v[4];
    float m1 = -3.402823466e38f, m2 = -3.402823466e38f;
#pragma unroll
    for (int k = 0; k < 4; ++k) {
        float4 a = xin[tid + k * NT];
        a.x *= 0.5f; a.y *= 0.5f; a.z *= 0.5f; a.w *= 0.5f;
        v[k] = a;
        float c[4] = {a.x, a.y, a.z, a.w};
#pragma unroll
        for (int j = 0; j < 4; ++j) {
            float hi = fmaxf(m1, c[j]);
            float lo = fminf(m1, c[j]);
            m1 = hi;
            m2 = fmaxf(m2, lo);
        }
    }

    // ---- Warp (max, 2nd-max) pair reduction
#pragma unroll
    for (int o = 16; o; o >>= 1) {
        float b1 = __shfl_xor_sync(0xffffffffu, m1, o);
        float b2 = __shfl_xor_sync(0xffffffffu, m2, o);
        float hi = fmaxf(m1, b1);
        float lo = fminf(m1, b1);
        m1 = hi;
        m2 = fmaxf(lo, fmaxf(m2, b2));
    }
    if (lane == 0) { sm1[wid] = m1; sm2[wid] = m2; }
    __syncthreads();

    // ---- Every thread combines the 8 warp pairs (cheap, avoids a broadcast barrier)
    float M1 = sm1[0], M2 = sm2[0];
#pragma unroll
    for (int w = 1; w < NW; ++w) {
        float b1 = sm1[w], b2 = sm2[w];
        float hi = fmaxf(M1, b1);
        float lo = fminf(M1, b1);
        M1 = hi;
        M2 = fmaxf(lo, fmaxf(M2, b2));
    }

    // ---- Bisection replayed scalar & redundantly by every thread.
    // Oracle sum(u^p) >= 1  <=>  count(Xs > t) >= 2            (two terms >= 0.9751 each)
    //                        or  count==1 && (M1-t)^p rounds to >= 1.0f
    const float P = 1.0f / 4095.0f;          // p = 1/(d-1), faithful to reference
    float tmin = M1 - 1.0f;
    float diff = (M1 - 0.015625f) - tmin;    // t_max - t_min; d^(1-alpha)=1/64 exact
    float t = tmin;
#pragma unroll 1
    for (int it = 0; it < 50; ++it) {
        diff *= 0.5f;
        t = tmin + diff;
        if (t == tmin) break;                // fp32 fixpoint: remaining iters are no-ops
        bool acc;
        if (M2 > t) {
            acc = true;                      // >=2 elements above t
        } else {
            float u = M1 - t;                // count<=1; sole positive term is (M1-t)^p
            acc = (u > 0.0f) && (powf(u, P) >= 1.0f);
        }
        if (acc) tmin = t;
    }

    // ---- Final Z at last tested t: per-thread partial sum over the rare positives
    float s = 0.0f;
#pragma unroll
    for (int k = 0; k < 4; ++k) {
        float c[4] = {v[k].x, v[k].y, v[k].z, v[k].w};
#pragma unroll
        for (int j = 0; j < 4; ++j) {
            float u = c[j] - t;
            if (u > 0.0f) s += powf(u, P);
        }
    }
#pragma unroll
    for (int o = 16; o; o >>= 1) s += __shfl_xor_sync(0xffffffffu, s, o);
    if (lane == 0) ssum[wid] = s;
    __syncthreads();
    float S = ssum[0];
#pragma unroll
    for (int w = 1; w < NW; ++w) S += ssum[w];

    // ---- Write full row: zeros everywhere except the ~2 positives (powf recomputed,
    //      identical rounding to the sum pass)
#pragma unroll
    for (int k = 0; k < 4; ++k) {
        float c[4] = {v[k].x, v[k].y, v[k].z, v[k].w};
        float o[4];
#pragma unroll
        for (int j = 0; j < 4; ++j) {
            float u = c[j] - t;
            o[j] = (u > 0.0f) ? (powf(u, P) / S) : 0.0f;
        }
        yout[tid + k * NT] = make_float4(o[0], o[1], o[2], o[3]);
    }
}

extern "C" void kernel_launch(void* const* d_in, const int* in_sizes, int n_in,
                              void* d_out, int out_size) {
    const float* X = (const float*)d_in[0];
    float*       Y = (float*)d_out;
    const int rows = out_size / D;   // 8*2048 = 16384
    entmax_bisect_kernel<<<rows, NT>>>(X, Y);
}

// round 5
// speedup vs baseline: 3.8009x; 1.7732x over previous
#include <cuda_runtime.h>
#include <math.h>

#define D  4096
#define NT 256
#define NW 8

// Global powf threshold: smallest u > 0 with powf(u, 1/4095) >= 1.0f (device libm).
__device__ float g_Uc;

__global__ void compute_uc_kernel() {
    const float P = 1.0f / 4095.0f;
    // powf is monotone near the boundary; bisect on the float bit pattern.
    unsigned lo = 0x3F000000u;  // 0.5f  -> powf = 0.99983f < 1
    unsigned hi = 0x3F800000u;  // 1.0f  -> powf = 1.0f    >= 1
    while (hi - lo > 1u) {
        unsigned mid = (lo + hi) >> 1;
        if (powf(__uint_as_float(mid), P) >= 1.0f) hi = mid; else lo = mid;
    }
    g_Uc = __uint_as_float(hi);
}

__global__ void __launch_bounds__(NT)
entmax_bisect_kernel(const float* __restrict__ X, float* __restrict__ Y) {
    __shared__ float sm1[NW];
    __shared__ float sm2[NW];
    __shared__ float ssum[NW];

    const int tid  = threadIdx.x;
    const int lane = tid & 31;
    const int wid  = tid >> 5;
    const size_t base = (size_t)blockIdx.x * D;

    const float4* __restrict__ xin  = reinterpret_cast<const float4*>(X + base);
    float4* __restrict__       yout = reinterpret_cast<float4*>(Y + base);

    const float Uc = g_Uc;

    // ---- Load row into registers (16 floats/thread), scale by (alpha-1)=0.5 (exact),
    //      track per-thread (max, second-max) including duplicates.
    float4 v[4];
    float m1 = -3.402823466e38f, m2 = -3.402823466e38f;
#pragma unroll
    for (int k = 0; k < 4; ++k) {
        float4 a = xin[tid + k * NT];
        a.x *= 0.5f; a.y *= 0.5f; a.z *= 0.5f; a.w *= 0.5f;
        v[k] = a;
        float c[4] = {a.x, a.y, a.z, a.w};
#pragma unroll
        for (int j = 0; j < 4; ++j) {
            float hi = fmaxf(m1, c[j]);
            float lo = fminf(m1, c[j]);
            m1 = hi;
            m2 = fmaxf(m2, lo);
        }
    }

    // ---- Warp (max, 2nd-max) pair reduction
#pragma unroll
    for (int o = 16; o; o >>= 1) {
        float b1 = __shfl_xor_sync(0xffffffffu, m1, o);
        float b2 = __shfl_xor_sync(0xffffffffu, m2, o);
        float hi = fmaxf(m1, b1);
        float lo = fminf(m1, b1);
        m1 = hi;
        m2 = fmaxf(lo, fmaxf(m2, b2));
    }
    if (lane == 0) { sm1[wid] = m1; sm2[wid] = m2; }
    __syncthreads();

    // ---- Every thread combines the 8 warp pairs
    float M1 = sm1[0], M2 = sm2[0];
#pragma unroll
    for (int w = 1; w < NW; ++w) {
        float b1 = sm1[w], b2 = sm2[w];
        float hi = fmaxf(M1, b1);
        float lo = fminf(M1, b1);
        M1 = hi;
        M2 = fmaxf(lo, fmaxf(M2, b2));
    }

    // ---- Bisection, scalar & redundant per thread. Pure ALU oracle:
    //   sum(u^p) >= 1  <=>  count(Xs > t) >= 2   (each term >= 0.975)
    //                   or  count==1 && powf(M1-t, p) rounds >= 1.0f  <=>  M1-t >= Uc
    float tmin = M1 - 1.0f;
    float diff = (M1 - 0.015625f) - tmin;    // t_max - t_min; d^(1-alpha)=1/64 exact
    float t = tmin;
#pragma unroll 1
    for (int it = 0; it < 50; ++it) {
        diff *= 0.5f;
        t = tmin + diff;
        if (t == tmin) break;                // fp32 fixpoint: remaining iters are no-ops
        if ((M2 > t) || ((M1 - t) >= Uc)) tmin = t;
    }

    // ---- Final Z at last tested t: partial sum over the rare positives (fast pow:
    //      u^(1/4095) compresses log error by p -> ~1e-8 relative, far inside tolerance)
    const float P = 1.0f / 4095.0f;
    float s = 0.0f;
#pragma unroll
    for (int k = 0; k < 4; ++k) {
        float c[4] = {v[k].x, v[k].y, v[k].z, v[k].w};
#pragma unroll
        for (int j = 0; j < 4; ++j) {
            float u = c[j] - t;
            if (u > 0.0f) s += __powf(u, P);
        }
    }
#pragma unroll
    for (int o = 16; o; o >>= 1) s += __shfl_xor_sync(0xffffffffu, s, o);
    if (lane == 0) ssum[wid] = s;
    __syncthreads();
    float S = ssum[0];
#pragma unroll
    for (int w = 1; w < NW; ++w) S += ssum[w];
    const float rS = 1.0f / S;

    // ---- Write full row: zeros everywhere except the ~2 positives
#pragma unroll
    for (int k = 0; k < 4; ++k) {
        float c[4] = {v[k].x, v[k].y, v[k].z, v[k].w};
        float o[4];
#pragma unroll
        for (int j = 0; j < 4; ++j) {
            float u = c[j] - t;
            o[j] = (u > 0.0f) ? (__powf(u, P) * rS) : 0.0f;
        }
        yout[tid + k * NT] = make_float4(o[0], o[1], o[2], o[3]);
    }
}

extern "C" void kernel_launch(void* const* d_in, const int* in_sizes, int n_in,
                              void* d_out, int out_size) {
    const float* X = (const float*)d_in[0];
    float*       Y = (float*)d_out;
    const int rows = out_size / D;   // 8*2048 = 16384
    compute_uc_kernel<<<1, 1>>>();
    entmax_bisect_kernel<<<rows, NT>>>(X, Y);
}